// round 12
// baseline (speedup 1.0000x reference)
#include <cuda_runtime.h>
#include <math.h>

#define NN    8192
#define HN    4096
#define QN    2048
#define MODES 16
#define ROWS  4096          /* BATCH*CH */
#define KSPL  8             /* forward m-splits */
#define MSPL  256           /* m per split = QN/KSPL */

/* fwd combo smem: [cls][m][row], 32 rows/block */
#define CMB_T 34            /* 32 rows + pad; even (float2), T mod 32 = 2 */
#define CMB_S 1096          /* 32*34+8; S mod 32 = 8, even */

// Scratch (__device__ globals: allocation-free rule)
__device__ float g_FBf[QN*32];             // fwd basis, grouped, x0.5 at m=0
__device__ float g_FBi[QN*32];             // inv basis, grouped
__device__ float g_partial[KSPL*32*ROWS];  // fwd partials TRANSPOSED [ks][c][row]
__device__ float g_C2[ROWS*32];            // irfft coefs, grouped A/B
__device__ float g_WrT[MODES*4096];        // weights transposed: [k][i*64+o]
__device__ float g_WiT[MODES*4096];

// Grouped column layout c' = 0..31:
//   j = c'&7, odd = (c'>>3)&1, k = 2j+odd
//   c' 0..7: cos even k   8..15: cos odd   16..23: sin even   24..31: sin odd
__global__ void init_tables(const float* __restrict__ wr,
                            const float* __restrict__ wi) {
    int idx = blockIdx.x * blockDim.x + threadIdx.x;
    if (idx >= QN * 32) return;   // 65536 == basis entries == weight entries
    {   // basis
        int m = idx >> 5, c = idx & 31;
        int j = c & 7;
        int kk = 2 * j + ((c >> 3) & 1);
        int t = (kk * m) & (NN - 1);
        float a = (float)t * (1.0f / (float)HN);
        float v = (c < 16) ? cospif(a) : sinpif(a);
        g_FBi[idx] = v;
        g_FBf[idx] = (m == 0) ? 0.5f * v : v;  // m=0 quartet double-counts x[0],x[4096]
    }
    {   // weight transpose: wr[(i*64+o)*16+k] -> g_WrT[k][i*64+o]
        int io = idx >> 4, k = idx & 15;
        g_WrT[k * 4096 + io] = wr[idx];
        g_WiT[k * 4096 + io] = wi[idx];
    }
}

// ---------------------------------------------------------------------------
// Forward (folded): partial_T[ks][c'][row] = sum_m combo_{cls}[row][m]*FBf[m][c']
// 32 rows/block, 128 threads, thread tile 2r x 4c -> ~21.5KB smem, high occ.
// Inner: LDS.64 + LDS.128 + 8 FFMA, register double-buffered.
// ks==0 blocks also add the m=2048 boundary term (cos/sin(pi k/2) pattern).
// ---------------------------------------------------------------------------
__global__ __launch_bounds__(128) void fwd_dft(const float* __restrict__ x) {
    __shared__ float  cmb[4 * CMB_S];     // 17.5 KB
    __shared__ float4 bs[32][8];          // 4 KB

    const int tid  = threadIdx.x;
    const int row0 = blockIdx.x * 32;
    const int ms0  = blockIdx.y * MSPL;
    const int tr   = tid >> 3;            // 0..15 -> rows 2tr, 2tr+1
    const int tc   = tid & 7;             // 0..7  -> cols 4*tc..4*tc+3
    const int cls  = tc >> 1;             // 0..3

    float acc[2][4];
    #pragma unroll
    for (int j = 0; j < 2; j++)
        #pragma unroll
        for (int q = 0; q < 4; q++) acc[j][q] = 0.f;

    for (int ch = 0; ch < MSPL / 32; ch++) {
        const int m0 = ms0 + ch * 32;

        // stage combos: thread (row, g), m = g + 8*jj
        #pragma unroll
        for (int i = 0; i < 2; i++) {
            int q   = tid + i * 128;
            int row = q >> 3;             // 0..31
            int g   = q & 7;
            const float* xr = x + (size_t)(row0 + row) * NN;
            #pragma unroll
            for (int jj = 0; jj < 4; jj++) {
                int mi = g + 8 * jj;
                int mm = m0 + mi;
                float v0 = xr[mm];
                float v1 = xr[HN - mm];
                float v2 = xr[HN + mm];
                float v3 = xr[(NN - mm) & (NN - 1)];
                float p = v0 + v3, q2 = v0 - v3;
                float r = v1 + v2, s  = v2 - v1;
                float* base = cmb + mi * CMB_T + row;
                base[0 * CMB_S] = p + r;    // even-cos
                base[1 * CMB_S] = p - r;    // odd-cos
                base[2 * CMB_S] = q2 + s;   // even-sin
                base[3 * CMB_S] = q2 - s;   // odd-sin
            }
        }
        // stage basis tile (32 m x 32 c)
        #pragma unroll
        for (int i = 0; i < 2; i++) {
            int q  = tid + i * 128;
            int k  = q >> 3;
            int cq = q & 7;
            bs[k][cq] = *(const float4*)(g_FBf + (size_t)(m0 + k) * 32 + 4 * cq);
        }
        __syncthreads();

        const float* cbase = cmb + cls * CMB_S + 2 * tr;
        float2 xv = *(const float2*)(cbase);
        float4 bv = bs[0][tc];
        #pragma unroll
        for (int m = 0; m < 32; m++) {
            float2 xvn; float4 bvn;
            if (m < 31) {                       // register double-buffer
                xvn = *(const float2*)(cbase + (m + 1) * CMB_T);
                bvn = bs[m + 1][tc];
            }
            acc[0][0] += xv.x * bv.x; acc[0][1] += xv.x * bv.y;
            acc[0][2] += xv.x * bv.z; acc[0][3] += xv.x * bv.w;
            acc[1][0] += xv.y * bv.x; acc[1][1] += xv.y * bv.y;
            acc[1][2] += xv.y * bv.z; acc[1][3] += xv.y * bv.w;
            xv = xvn; bv = bvn;
        }
        __syncthreads();
    }

    // m=2048 boundary (only ks==0 blocks): c<8 (cos even k=2j): (xa+xb)*(-1)^j
    //                                      c>=24 (sin odd k):   (xa-xb)*(-1)^j
    if (blockIdx.y == 0 && (tc < 2 || tc >= 6)) {
        #pragma unroll
        for (int j = 0; j < 2; j++) {
            const float* xr = x + (size_t)(row0 + 2 * tr + j) * NN;
            float xa = xr[QN], xb = xr[3 * QN];
            float t  = (tc < 2) ? (xa + xb) : (xa - xb);
            #pragma unroll
            for (int q = 0; q < 4; q++) {
                int cj = (4 * tc + q) & 7;
                acc[j][q] += (cj & 1) ? -t : t;
            }
        }
    }

    // epilogue: transposed store [ks][c][row], float2 over the 2 rows
    #pragma unroll
    for (int q = 0; q < 4; q++) {
        int c = 4 * tc + q;
        *(float2*)(g_partial + ((size_t)blockIdx.y * 32 + c) * ROWS + row0 + 2 * tr)
            = make_float2(acc[0][q], acc[1][q]);
    }
}

// ---------------------------------------------------------------------------
// Fused reduce + mix: grid (16 k, 16 bg), 256 thr. Reduces the K-splits with
// fully coalesced reads from the transposed partials (256 consecutive rows per
// column), then applies complex weights from smem-staged transposed copies.
// ---------------------------------------------------------------------------
__global__ __launch_bounds__(256) void mixred() {
    __shared__ float sWr[64 * 64];
    __shared__ float sWi[64 * 64];
    __shared__ float sXc[256], sXs[256];
    const int k   = blockIdx.x;
    const int bg  = blockIdx.y;
    const int tid = threadIdx.x;

    const int cA = (k & 1) ? 8 + (k >> 1) : (k >> 1);
    const int cS = cA + 16;

    const float* wrk = g_WrT + (size_t)k * 4096;
    const float* wik = g_WiT + (size_t)k * 4096;
    #pragma unroll
    for (int i = 0; i < 4; i++) {
        int q = tid + i * 256;
        ((float4*)sWr)[q] = ((const float4*)wrk)[q];
        ((float4*)sWi)[q] = ((const float4*)wik)[q];
    }
    {   // fused K-split reduction, coalesced: row = bg*256 + tid
        int row = bg * 256 + tid;
        float xc = 0.f, xs = 0.f;
        #pragma unroll
        for (int ks = 0; ks < KSPL; ks++) {
            xc += g_partial[((size_t)ks * 32 + cA) * ROWS + row];
            xs += g_partial[((size_t)ks * 32 + cS) * ROWS + row];
        }
        sXc[tid] = xc;
        sXs[tid] = xs;
    }
    __syncthreads();

    const int o  = tid & 63;
    const int bl = tid >> 6;
    float cre = 0.f, cim = 0.f;
    #pragma unroll 8
    for (int i = 0; i < 64; i++) {
        float a   = sXc[bl * 64 + i];
        float s   = sXs[bl * 64 + i];
        float wre = sWr[i * 64 + o];
        float wim = sWi[i * 64 + o];
        cre += a * wre + s * wim;
        cim += a * wim - s * wre;
    }
    const float invN = 1.0f / (float)NN;
    float A  = (k == 0 ? cre : 2.f * cre) * invN;
    float Bc = (k == 0 ? 0.f : -2.f * cim * invN);
    int rowo = (bg * 4 + bl) * 64 + o;
    g_C2[(size_t)rowo * 32 + cA] = A;
    g_C2[(size_t)rowo * 32 + cS] = Bc;
}

// ---------------------------------------------------------------------------
// Inverse (folded): SPREAD-n -- thread owns n1 = idx (0..1023), n2 = n1+1024;
// all 8 scalar stores warp-coalesced. Group-accumulator consumption, ~90 regs.
// 128 thr, 32 rows/block -> 1024 blocks. n=0 wraps are exact duplicates;
// n1==0 emits n=2048/6144.
// ---------------------------------------------------------------------------
__global__ __launch_bounds__(128) void inv_dft(float* __restrict__ y) {
    __shared__ float sC[32 * 32];
    const int tid  = threadIdx.x;
    const int row0 = blockIdx.y * 32;
    const int n1   = blockIdx.x * 128 + tid;    // 0..1023
    const int n2   = n1 + 1024;                 // 1024..2047

    #pragma unroll
    for (int i = 0; i < 2; i++) {
        int q = tid + i * 128;
        *(float4*)(sC + 4 * q) = *(const float4*)(g_C2 + (size_t)row0 * 32 + 4 * q);
    }

    float b1[32], b2[32];
    #pragma unroll
    for (int i = 0; i < 8; i++) {
        float4 v = *(const float4*)(g_FBi + (size_t)n1 * 32 + 4 * i);
        b1[4*i+0] = v.x; b1[4*i+1] = v.y; b1[4*i+2] = v.z; b1[4*i+3] = v.w;
        float4 u = *(const float4*)(g_FBi + (size_t)n2 * 32 + 4 * i);
        b2[4*i+0] = u.x; b2[4*i+1] = u.y; b2[4*i+2] = u.z; b2[4*i+3] = u.w;
    }
    __syncthreads();

    const int nrev1 = (NN - n1) & (NN - 1);     // 0 when n1==0 (dup, benign)
    const int nm1   = HN - n1,  np1 = HN + n1;
    const int nrev2 = NN - n2;
    const int nm2   = HN - n2,  np2 = HN + n2;

    for (int r = 0; r < 32; r++) {
        const float* cp = sC + r * 32;
        // a[0]=E (cos-even), a[1]=F (cos-odd), a[2]=G (sin-even), a[3]=H (sin-odd)
        float a1[4] = {0.f, 0.f, 0.f, 0.f};
        float a2[4] = {0.f, 0.f, 0.f, 0.f};
        #pragma unroll
        for (int i = 0; i < 8; i++) {
            float4 v = *(const float4*)(cp + 4 * i);   // broadcast LDS.128
            int g = i >> 1;
            a1[g] += v.x * b1[4*i] + v.y * b1[4*i+1] + v.z * b1[4*i+2] + v.w * b1[4*i+3];
            a2[g] += v.x * b2[4*i] + v.y * b2[4*i+1] + v.z * b2[4*i+2] + v.w * b2[4*i+3];
        }
        float P1 = a1[0] + a1[1], Q1 = a1[0] - a1[1];
        float R1 = a1[2] + a1[3], S1 = a1[2] - a1[3];
        float P2 = a2[0] + a2[1], Q2 = a2[0] - a2[1];
        float R2 = a2[2] + a2[3], S2 = a2[2] - a2[3];
        size_t rb = (size_t)(row0 + r) * NN;

        y[rb + n1]    = P1 + R1;
        y[rb + nrev1] = P1 - R1;     // n1==0: dup of y[0] (R1==0), benign
        y[rb + nm1]   = Q1 - S1;     // n1==0: dup of np1 (S1==0), benign
        y[rb + np1]   = Q1 + S1;
        y[rb + n2]    = P2 + R2;
        y[rb + nrev2] = P2 - R2;
        y[rb + nm2]   = Q2 - S2;
        y[rb + np2]   = Q2 + S2;

        if (n1 == 0) {   // outputs n=2048, 6144
            float da = 0.f, db = 0.f;
            #pragma unroll
            for (int i = 0; i < 8; i++) {
                float sg = (i & 1) ? -1.f : 1.f;
                da += sg * cp[i];        // A_{2j} * (-1)^j
                db += sg * cp[24 + i];   // B_{2j+1} * (-1)^j
            }
            y[rb + QN]     = da + db;
            y[rb + 3 * QN] = da - db;
        }
    }
}

// ---------------------------------------------------------------------------
extern "C" void kernel_launch(void* const* d_in, const int* in_sizes, int n_in,
                              void* d_out, int out_size) {
    const float* x  = (const float*)d_in[0];
    const float* wr = (const float*)d_in[1];
    const float* wi = (const float*)d_in[2];
    float*       y  = (float*)d_out;

    init_tables<<<(QN * 32 + 255) / 256, 256>>>(wr, wi);
    fwd_dft<<<dim3(ROWS / 32, KSPL), 128>>>(x);
    mixred<<<dim3(MODES, 16), 256>>>();
    inv_dft<<<dim3(QN / 2 / 128, ROWS / 32), 128>>>(y);   // 4th -> profiled
}